// round 16
// baseline (speedup 1.0000x reference)
#include <cuda_runtime.h>

#define NN   8192     // N == E == 8192
#define DIM  256
#define CAP  192      // per-row/col capacity: mean 81.9, sigma 9.0 -> +12 sigma

struct __align__(8) Ent { unsigned int k; float v; };

// ELL sparse structures (device globals -- no allocation anywhere)
__device__ Ent  g_Af[(size_t)NN * CAP];
__device__ Ent  g_AT[(size_t)NN * CAP];
__device__ Ent  g_Bf[(size_t)NN * CAP];
__device__ Ent  g_BT[(size_t)NN * CAP];
__device__ int  g_cAf[NN], g_cAT[NN], g_cBf[NN], g_cBT[NN];
__device__ float g_buf0[(size_t)NN * DIM];
__device__ float g_buf1[(size_t)NN * DIM];

// Side stream + events, created at program load (static initializer: before
// the harness's memory baseline, never during capture). Inside kernel_launch
// only capture-legal ops are used (launches, event record, stream-wait).
struct ForkResources {
    cudaStream_t s2;
    cudaEvent_t evA, evB, evTA, evTB;
    ForkResources() {
        cudaStreamCreateWithFlags(&s2, cudaStreamNonBlocking);
        cudaEventCreateWithFlags(&evA,  cudaEventDisableTiming);
        cudaEventCreateWithFlags(&evB,  cudaEventDisableTiming);
        cudaEventCreateWithFlags(&evTA, cudaEventDisableTiming);
        cudaEventCreateWithFlags(&evTB, cudaEventDisableTiming);
    }
};
static ForkResources g_fork;

__device__ __forceinline__ unsigned long long dup2(float a) {
    unsigned long long r;
    asm("mov.b64 %0, {%1, %2};" : "=l"(r) : "f"(a), "f"(a));
    return r;
}
// Packed dual FMA (Blackwell f32x2)
__device__ __forceinline__ void fma2(unsigned long long& d,
                                     unsigned long long a,
                                     unsigned long long b) {
    asm("fma.rn.f32x2 %0, %1, %2, %0;" : "+l"(d) : "l"(a), "l"(b));
}

__global__ void zero_cnts() {
    int i = blockIdx.x * blockDim.x + threadIdx.x;
    if (i < NN) { g_cAf[i] = 0; g_cAT[i] = 0; g_cBf[i] = 0; g_cBT[i] = 0; }
}

// Pure-streaming scan -> FORWARD ELL only. No scattered traffic: loads are a
// clean 4x-float4 stream, stores are ~5 coalesced Ents per warp, one atomic
// per warp. H1 test: without the interleaved transposed scatter this should
// run near the streaming ceiling (~45us vs 61us).
__global__ __launch_bounds__(256)
void scan_forward(const float4* __restrict__ M4,
                  Ent* __restrict__ F, int* __restrict__ cF) {
    const unsigned int wg   = (blockIdx.x * blockDim.x + threadIdx.x) >> 5;
    const unsigned int lane = threadIdx.x & 31;
    const unsigned int row  = wg >> 4;           // 16 warp-segments per row
    const unsigned int seg  = wg & 15;
    const size_t base4 = (size_t)row * 2048 + seg * 128;   // float4 units

    float4 q[4];
    #pragma unroll
    for (int p = 0; p < 4; ++p) q[p] = M4[base4 + p * 32 + lane];

    float vals[16];
    #pragma unroll
    for (int p = 0; p < 4; ++p) {
        vals[p * 4 + 0] = q[p].x; vals[p * 4 + 1] = q[p].y;
        vals[p * 4 + 2] = q[p].z; vals[p * 4 + 3] = q[p].w;
    }
    const unsigned int c0 = seg * 512 + lane * 4;

    int cnt = 0;
    #pragma unroll
    for (int s = 0; s < 16; ++s) cnt += (vals[s] != 0.0f);

    // warp inclusive prefix scan (5 shfls)
    int incl = cnt;
    #pragma unroll
    for (int d = 1; d < 32; d <<= 1) {
        int t = __shfl_up_sync(0xffffffffu, incl, d);
        if ((int)lane >= d) incl += t;
    }
    const int total = __shfl_sync(0xffffffffu, incl, 31);
    if (total == 0) return;

    int base = 0;
    if (lane == 0) base = atomicAdd(&cF[row], total);
    base = __shfl_sync(0xffffffffu, base, 0);

    int pos = base + (incl - cnt);
    #pragma unroll
    for (int s = 0; s < 16; ++s) {
        if (vals[s] != 0.0f) {
            unsigned int col = c0 + (s >> 2) * 128 + (s & 3);
            if (pos < CAP) F[(size_t)row * CAP + pos] = Ent{col, vals[s]};
            ++pos;
        }
    }
}

// Transpose pass: read the compact forward list (5.4MB), scatter into the
// transposed ELL. Warp per row, ~3 entries per lane; latency-bound scatter,
// runs concurrently with the next streaming scan / spmm on the other stream.
__global__ __launch_bounds__(256)
void build_transpose(const Ent* __restrict__ F, const int* __restrict__ cF,
                     Ent* __restrict__ T, int* __restrict__ cT) {
    const unsigned int row  = blockIdx.x * 8 + (threadIdx.x >> 5);
    const unsigned int lane = threadIdx.x & 31;
    int n = cF[row];
    if (n > CAP) n = CAP;
    const Ent* fp = F + (size_t)row * CAP;
    for (int j = lane; j < n; j += 32) {
        Ent e = fp[j];
        int pt = atomicAdd(&cT[e.k], 1);
        if (pt < CAP) T[(size_t)e.k * CAP + pt] = Ent{row, e.v};
    }
}

// C[row, :] = sum_j ell[row][j].v * D[ell[row][j].k, :]   (D: [NN x 256])
// 2 warps per row, each owns 128 columns. 8 entries/iter: entry list read as
// 4x uint4 (each uint4 = TWO Ent; block for entries j..j+7 starts at uint4
// index j>>1), gathers via 32-bit byte offsets (k << 10). Default launch
// bounds (regs=32, occ ~80%): the measured optimum.
template<bool LEAKY>
__global__ __launch_bounds__(256)
void spmm(const Ent* __restrict__ ell, const int* __restrict__ cnt,
          const float* __restrict__ D, float* __restrict__ C) {
    const int w    = threadIdx.x >> 5;
    const int row  = blockIdx.x * 4 + (w >> 1);
    const int half = w & 1;
    const int lane = threadIdx.x & 31;
    const uint4* epq = (const uint4*)(ell + (size_t)row * CAP);
    int n = cnt[row];
    if (n > CAP) n = CAP;

    const char* Db = (const char*)D + half * 512 + lane * 16;

    unsigned long long acc0 = 0, acc1 = 0;
    int j = 0;
    for (; j + 8 <= n; j += 8) {
        const int qb = j >> 1;                 // uint4 index: 2 entries each
        uint4 q0 = epq[qb + 0];
        uint4 q1 = epq[qb + 1];
        uint4 q2 = epq[qb + 2];
        uint4 q3 = epq[qb + 3];
        unsigned int ks[8] = {q0.x, q0.z, q1.x, q1.z,
                              q2.x, q2.z, q3.x, q3.z};
        unsigned int vs[8] = {q0.y, q0.w, q1.y, q1.w,
                              q2.y, q2.w, q3.y, q3.w};
        ulonglong2 p[8];
        #pragma unroll
        for (int t = 0; t < 8; ++t)
            p[t] = *(const ulonglong2*)(Db + ((size_t)ks[t] << 10));
        #pragma unroll
        for (int t = 0; t < 8; ++t) {
            unsigned long long v = dup2(__uint_as_float(vs[t]));
            fma2(acc0, v, p[t].x);
            fma2(acc1, v, p[t].y);
        }
    }
    {
        const Ent* ep = (const Ent*)epq;
        for (; j < n; ++j) {
            Ent e0 = ep[j];
            ulonglong2 p0 = *(const ulonglong2*)(Db + ((size_t)e0.k << 10));
            unsigned long long v0 = dup2(e0.v);
            fma2(acc0, v0, p0.x); fma2(acc1, v0, p0.y);
        }
    }

    float2 f0 = *(float2*)&acc0, f1 = *(float2*)&acc1;
    if (LEAKY) {
        f0.x = fmaxf(f0.x, 0.2f * f0.x);  f0.y = fmaxf(f0.y, 0.2f * f0.y);
        f1.x = fmaxf(f1.x, 0.2f * f1.x);  f1.y = fmaxf(f1.y, 0.2f * f1.y);
    }
    *(float4*)(C + (size_t)row * DIM + half * 128 + lane * 4) =
        make_float4(f0.x, f0.y, f1.x, f1.y);
}

extern "C" void kernel_launch(void* const* d_in, const int* in_sizes, int n_in,
                              void* d_out, int out_size) {
    // metadata order: inp_adj (B) [E,N], att_adj (A) [N,E], embs [N,D]
    const float* inp_adj = (const float*)d_in[0];
    const float* att_adj = (const float*)d_in[1];
    const float* embs    = (const float*)d_in[2];
    float* out = (float*)d_out;

    Ent *Af, *AT, *Bf, *BT;
    int *cAf, *cAT, *cBf, *cBT;
    float *buf0, *buf1;
    cudaGetSymbolAddress((void**)&Af,  g_Af);
    cudaGetSymbolAddress((void**)&AT,  g_AT);
    cudaGetSymbolAddress((void**)&Bf,  g_Bf);
    cudaGetSymbolAddress((void**)&BT,  g_BT);
    cudaGetSymbolAddress((void**)&cAf, g_cAf);
    cudaGetSymbolAddress((void**)&cAT, g_cAT);
    cudaGetSymbolAddress((void**)&cBf, g_cBf);
    cudaGetSymbolAddress((void**)&cBT, g_cBT);
    cudaGetSymbolAddress((void**)&buf0, g_buf0);
    cudaGetSymbolAddress((void**)&buf1, g_buf1);

    const int sgrid = NN * 16 / 8;   // 16384 blocks per scan
    const int tgrid = NN / 8;        // 1024 blocks per transpose
    const int g = NN / 4;            // 2048 CTAs per spmm

    // DAG:
    //   main: zero → scanA ─────→ scanB ──────────→ spmm1 → spmm2 → spmm3 → spmm4
    //   side:         └→ transA (∥ scanB) └→ transB (∥ spmm1)
    // spmm1 waits transA; spmm2 waits transB.
    zero_cnts<<<32, 256>>>();

    scan_forward<<<sgrid, 256>>>((const float4*)att_adj, Af, cAf);
    cudaEventRecord(g_fork.evA, 0);

    scan_forward<<<sgrid, 256>>>((const float4*)inp_adj, Bf, cBf);
    cudaEventRecord(g_fork.evB, 0);

    cudaStreamWaitEvent(g_fork.s2, g_fork.evA, 0);
    build_transpose<<<tgrid, 256, 0, g_fork.s2>>>(Af, cAf, AT, cAT);
    cudaEventRecord(g_fork.evTA, g_fork.s2);

    cudaStreamWaitEvent(g_fork.s2, g_fork.evB, 0);
    build_transpose<<<tgrid, 256, 0, g_fork.s2>>>(Bf, cBf, BT, cBT);
    cudaEventRecord(g_fork.evTB, g_fork.s2);

    cudaStreamWaitEvent(0, g_fork.evTA, 0);
    spmm<false><<<g, 256>>>(AT, cAT, embs, buf0);            // u1 = A^T @ embs

    cudaStreamWaitEvent(0, g_fork.evTB, 0);
    spmm<false><<<g, 256>>>(BT, cBT, buf0, buf1);            // t  = B^T @ u1
    spmm<false><<<g, 256>>>(Bf, cBf, buf1, buf0);            // v  = B  @ t
    spmm<true ><<<g, 256>>>(Af, cAf, buf0, out);             // out = leaky(A @ v)
}

// round 17
// speedup vs baseline: 1.0172x; 1.0172x over previous
#include <cuda_runtime.h>

#define NN   8192     // N == E == 8192
#define DIM  256
#define CAP  192      // per-row/col capacity: mean 81.9, sigma 9.0 -> +12 sigma

struct __align__(8) Ent { unsigned int k; float v; };

// ELL sparse structures (device globals -- no allocation anywhere)
__device__ Ent  g_Af[(size_t)NN * CAP];
__device__ Ent  g_AT[(size_t)NN * CAP];
__device__ Ent  g_Bf[(size_t)NN * CAP];
__device__ Ent  g_BT[(size_t)NN * CAP];
__device__ int  g_cAf[NN], g_cAT[NN], g_cBf[NN], g_cBT[NN];
__device__ float g_buf0[(size_t)NN * DIM];
__device__ float g_buf1[(size_t)NN * DIM];

// Side stream + events, created at program load (static initializer: before
// the harness's memory baseline, never during capture). Inside kernel_launch
// only capture-legal ops are used (launches, event record, stream-wait).
struct ForkResources {
    cudaStream_t s2;
    cudaEvent_t evFork, evJoin;
    ForkResources() {
        cudaStreamCreateWithFlags(&s2, cudaStreamNonBlocking);
        cudaEventCreateWithFlags(&evFork, cudaEventDisableTiming);
        cudaEventCreateWithFlags(&evJoin, cudaEventDisableTiming);
    }
};
static ForkResources g_fork;

__device__ __forceinline__ unsigned long long dup2(float a) {
    unsigned long long r;
    asm("mov.b64 %0, {%1, %2};" : "=l"(r) : "f"(a), "f"(a));
    return r;
}
// Packed dual FMA (Blackwell f32x2)
__device__ __forceinline__ void fma2(unsigned long long& d,
                                     unsigned long long a,
                                     unsigned long long b) {
    asm("fma.rn.f32x2 %0, %1, %2, %0;" : "+l"(d) : "l"(a), "l"(b));
}

__global__ void zero_cnts() {
    int i = blockIdx.x * blockDim.x + threadIdx.x;
    if (i < NN) { g_cAf[i] = 0; g_cAT[i] = 0; g_cBf[i] = 0; g_cBT[i] = 0; }
}

// Streaming scan -> forward + transposed ELL (the measured-optimal build:
// MLP=4, shfl prefix scan, one forward atomicAdd per warp, single-phase emit
// with per-nonzero transposed atomics; ~61us each, a robust ceiling across
// 7 structural variants).
__global__ __launch_bounds__(256)
void build_both(const float4* __restrict__ M4,
                Ent* __restrict__ F, int* __restrict__ cF,
                Ent* __restrict__ T, int* __restrict__ cT) {
    const unsigned int wg   = (blockIdx.x * blockDim.x + threadIdx.x) >> 5;
    const unsigned int lane = threadIdx.x & 31;
    const unsigned int row  = wg >> 4;           // 16 warp-segments per row
    const unsigned int seg  = wg & 15;
    const size_t base4 = (size_t)row * 2048 + seg * 128;   // float4 units

    float4 q[4];
    #pragma unroll
    for (int p = 0; p < 4; ++p) q[p] = M4[base4 + p * 32 + lane];

    float vals[16];
    #pragma unroll
    for (int p = 0; p < 4; ++p) {
        vals[p * 4 + 0] = q[p].x; vals[p * 4 + 1] = q[p].y;
        vals[p * 4 + 2] = q[p].z; vals[p * 4 + 3] = q[p].w;
    }
    const unsigned int c0 = seg * 512 + lane * 4;

    int cnt = 0;
    #pragma unroll
    for (int s = 0; s < 16; ++s) cnt += (vals[s] != 0.0f);

    int incl = cnt;
    #pragma unroll
    for (int d = 1; d < 32; d <<= 1) {
        int t = __shfl_up_sync(0xffffffffu, incl, d);
        if ((int)lane >= d) incl += t;
    }
    const int total = __shfl_sync(0xffffffffu, incl, 31);
    if (total == 0) return;

    int base = 0;
    if (lane == 0) base = atomicAdd(&cF[row], total);
    base = __shfl_sync(0xffffffffu, base, 0);

    int pos = base + (incl - cnt);
    #pragma unroll
    for (int s = 0; s < 16; ++s) {
        if (vals[s] != 0.0f) {
            unsigned int col = c0 + (s >> 2) * 128 + (s & 3);
            if (pos < CAP) F[(size_t)row * CAP + pos] = Ent{col, vals[s]};
            ++pos;
            int pt = atomicAdd(&cT[col], 1);
            if (pt < CAP) T[(size_t)col * CAP + pt] = Ent{row, vals[s]};
        }
    }
}

// C[row, :] = sum_j ell[row][j].v * D[ell[row][j].k, :]   (D: [NN x 256])
// 2 warps per row, 8 entries/iter, 8 outstanding 16B gathers per lane
// (the measured optimum). PDL-aware: under programmatic dependent launch the
// prologue overlaps the previous kernel's drain; cudaGridDependencySynchronize
// gates only the dependent reads. SYNC_EARLY=true puts the sync before the
// cnt load (spmm1: cnt is produced by the PDL primary build_A); false puts it
// after cnt, before the D gathers (spmm2-4: cnt/entries come from the builds,
// which completed before the primary spmm even started -- only D is unsafe).
// Without the PDL launch attribute the sync is a no-op.
template<bool LEAKY, bool SYNC_EARLY>
__global__ __launch_bounds__(256)
void spmm(const Ent* __restrict__ ell, const int* __restrict__ cnt,
          const float* __restrict__ D, float* __restrict__ C) {
    const int w    = threadIdx.x >> 5;
    const int row  = blockIdx.x * 4 + (w >> 1);
    const int half = w & 1;
    const int lane = threadIdx.x & 31;
    const uint4* epq = (const uint4*)(ell + (size_t)row * CAP);

    if (SYNC_EARLY) cudaGridDependencySynchronize();

    int n = cnt[row];
    if (n > CAP) n = CAP;

    if (!SYNC_EARLY) cudaGridDependencySynchronize();

    const char* Db = (const char*)D + half * 512 + lane * 16;

    unsigned long long acc0 = 0, acc1 = 0;
    int j = 0;
    for (; j + 8 <= n; j += 8) {
        const int qb = j >> 1;                 // uint4 index: 2 entries each
        uint4 q0 = epq[qb + 0];
        uint4 q1 = epq[qb + 1];
        uint4 q2 = epq[qb + 2];
        uint4 q3 = epq[qb + 3];
        unsigned int ks[8] = {q0.x, q0.z, q1.x, q1.z,
                              q2.x, q2.z, q3.x, q3.z};
        unsigned int vs[8] = {q0.y, q0.w, q1.y, q1.w,
                              q2.y, q2.w, q3.y, q3.w};
        ulonglong2 p[8];
        #pragma unroll
        for (int t = 0; t < 8; ++t)
            p[t] = *(const ulonglong2*)(Db + ((size_t)ks[t] << 10));
        #pragma unroll
        for (int t = 0; t < 8; ++t) {
            unsigned long long v = dup2(__uint_as_float(vs[t]));
            fma2(acc0, v, p[t].x);
            fma2(acc1, v, p[t].y);
        }
    }
    {
        const Ent* ep = (const Ent*)epq;
        for (; j < n; ++j) {
            Ent e0 = ep[j];
            ulonglong2 p0 = *(const ulonglong2*)(Db + ((size_t)e0.k << 10));
            unsigned long long v0 = dup2(e0.v);
            fma2(acc0, v0, p0.x); fma2(acc1, v0, p0.y);
        }
    }

    float2 f0 = *(float2*)&acc0, f1 = *(float2*)&acc1;
    if (LEAKY) {
        f0.x = fmaxf(f0.x, 0.2f * f0.x);  f0.y = fmaxf(f0.y, 0.2f * f0.y);
        f1.x = fmaxf(f1.x, 0.2f * f1.x);  f1.y = fmaxf(f1.y, 0.2f * f1.y);
    }
    *(float4*)(C + (size_t)row * DIM + half * 128 + lane * 4) =
        make_float4(f0.x, f0.y, f1.x, f1.y);
}

// Launch helper: spmm with the programmatic-stream-serialization attribute.
template<bool LEAKY, bool SYNC_EARLY>
static void launch_spmm_pdl(int grid, const Ent* ell, const int* cnt,
                            const float* D, float* C) {
    cudaLaunchConfig_t cfg = {};
    cfg.gridDim  = dim3((unsigned)grid);
    cfg.blockDim = dim3(256);
    cfg.stream   = 0;
    cudaLaunchAttribute attr[1];
    attr[0].id = cudaLaunchAttributeProgrammaticStreamSerialization;
    attr[0].val.programmaticStreamSerializationAllowed = 1;
    cfg.attrs = attr;
    cfg.numAttrs = 1;
    cudaLaunchKernelEx(&cfg, &spmm<LEAKY, SYNC_EARLY>, ell, cnt, D, C);
}

extern "C" void kernel_launch(void* const* d_in, const int* in_sizes, int n_in,
                              void* d_out, int out_size) {
    // metadata order: inp_adj (B) [E,N], att_adj (A) [N,E], embs [N,D]
    const float* inp_adj = (const float*)d_in[0];
    const float* att_adj = (const float*)d_in[1];
    const float* embs    = (const float*)d_in[2];
    float* out = (float*)d_out;

    Ent *Af, *AT, *Bf, *BT;
    int *cAf, *cAT, *cBf, *cBT;
    float *buf0, *buf1;
    cudaGetSymbolAddress((void**)&Af,  g_Af);
    cudaGetSymbolAddress((void**)&AT,  g_AT);
    cudaGetSymbolAddress((void**)&Bf,  g_Bf);
    cudaGetSymbolAddress((void**)&BT,  g_BT);
    cudaGetSymbolAddress((void**)&cAf, g_cAf);
    cudaGetSymbolAddress((void**)&cAT, g_cAT);
    cudaGetSymbolAddress((void**)&cBf, g_cBf);
    cudaGetSymbolAddress((void**)&cBT, g_cBT);
    cudaGetSymbolAddress((void**)&buf0, g_buf0);
    cudaGetSymbolAddress((void**)&buf1, g_buf1);

    const int bgrid = NN * 16 / 8;   // 16384 blocks per build
    const int g = NN / 4;            // 2048 CTAs per spmm, 2 warps per row

    // R13 schedule (best measured) + PDL on the serial spmm chain:
    //   zero ─┬─ build_A ─PDL─ spmm1(AT) ─PDL┬─ spmm2 ─PDL─ spmm3 ─PDL─ spmm4
    //         └─ build_B (side stream) ──────┘
    zero_cnts<<<32, 256>>>();

    cudaEventRecord(g_fork.evFork, 0);
    cudaStreamWaitEvent(g_fork.s2, g_fork.evFork, 0);

    build_both<<<bgrid, 256, 0, g_fork.s2>>>(
        (const float4*)inp_adj, Bf, cBf, BT, cBT);           // B on side stream
    build_both<<<bgrid, 256>>>(
        (const float4*)att_adj, Af, cAf, AT, cAT);           // A on main stream

    // spmm1: cnt/entries come from the PDL primary (build_A) -> sync early
    launch_spmm_pdl<false, true >(g, AT, cAT, embs, buf0);   // u1 = A^T @ embs

    cudaEventRecord(g_fork.evJoin, g_fork.s2);
    cudaStreamWaitEvent(0, g_fork.evJoin, 0);                // join before BT use

    // spmm2-4: cnt/entries from the builds (complete before the primary
    // spmm started); only D depends on the primary -> sync late
    launch_spmm_pdl<false, false>(g, BT, cBT, buf0, buf1);   // t  = B^T @ u1
    launch_spmm_pdl<false, false>(g, Bf, cBf, buf1, buf0);   // v  = B  @ t
    launch_spmm_pdl<true,  false>(g, Af, cAf, buf0, out);    // out = leaky(A @ v)
}